// round 1
// baseline (speedup 1.0000x reference)
#include <cuda_runtime.h>
#include <cstdint>
#include <cstddef>

typedef unsigned long long u64;

#define B_TOT 2048
#define N_TOK 49
#define CDIM  256
#define NHEAD 8
#define HDIM  32
#define M_ROWS (B_TOT * N_TOK)      // 100352

// -------- scratch (device globals: no allocation allowed) --------
__device__ __align__(16) float g_q[(size_t)B_TOT * NHEAD * N_TOK * HDIM];
__device__ __align__(16) float g_k[(size_t)B_TOT * NHEAD * N_TOK * HDIM];
__device__ __align__(16) float g_v[(size_t)B_TOT * NHEAD * N_TOK * HDIM];
__device__ __align__(16) float g_attn_out[(size_t)M_ROWS * CDIM];
__device__ float g_bias[NHEAD * N_TOK * N_TOK];

// -------- packed-fp32 helpers (fma.rn.f32x2, sm_100+) --------
__device__ __forceinline__ u64 pack2(float x, float y) {
    u64 r; asm("mov.b64 %0,{%1,%2};" : "=l"(r) : "f"(x), "f"(y)); return r;
}
__device__ __forceinline__ u64 pack2b(float x) {
    u64 r; asm("mov.b64 %0,{%1,%1};" : "=l"(r) : "f"(x)); return r;
}
__device__ __forceinline__ u64 ffma2(u64 a, u64 b, u64 c) {
    u64 d; asm("fma.rn.f32x2 %0,%1,%2,%3;" : "=l"(d) : "l"(a), "l"(b), "l"(c)); return d;
}
__device__ __forceinline__ float2 unpack2(u64 v) {
    float lo, hi; asm("mov.b64 {%0,%1},%2;" : "=f"(lo), "=f"(hi) : "l"(v));
    return make_float2(lo, hi);
}

// -------- relative position bias precompute --------
__global__ void bias_kernel(const float* __restrict__ table) {
    int t = blockIdx.x * blockDim.x + threadIdx.x;
    if (t >= NHEAD * N_TOK * N_TOK) return;
    int h  = t / (N_TOK * N_TOK);
    int ij = t - h * (N_TOK * N_TOK);
    int i = ij / N_TOK, j = ij - i * N_TOK;
    int ri = i / 7, ci = i - ri * 7;
    int rj = j / 7, cj = j - rj * 7;
    int idx = (ri - rj + 6) * 13 + (ci - cj + 6);
    g_bias[t] = table[idx * NHEAD + h];
}

// -------- SGEMM: C[M][Ncols] = A[M][256] @ W[Ncols][256]^T + bias --------
// BM=BN=128, BK=16, 256 threads, 8x8 microtile, fp32x2 packed FMA.
// MODE 0: QKV epilogue (split + scale q). MODE 1: proj epilogue (write d_out).
template<int MODE>
__global__ void __launch_bounds__(256) gemm_kernel(const float* __restrict__ A_in,
                                                   const float* __restrict__ W,
                                                   const float* __restrict__ bias,
                                                   float* __restrict__ out) {
    __shared__ __align__(16) float As[16][128];
    __shared__ __align__(16) float Bs[16][128];

    const float* A = (MODE == 0) ? A_in : g_attn_out;
    const int tid = threadIdx.x;
    const int bm = blockIdx.x, bn = blockIdx.y;
    const int r = tid >> 4;      // 0..15 -> rows r*8 .. r*8+7
    const int c = tid & 15;      // 0..15 -> cols c*8 .. c*8+7

    u64 acc[8][4];
#pragma unroll
    for (int i = 0; i < 8; i++)
#pragma unroll
        for (int j = 0; j < 4; j++) acc[i][j] = 0ull;

    const float* Ab = A + (size_t)bm * 128 * 256;
    const float* Wb = W + (size_t)bn * 128 * 256;

    for (int k0 = 0; k0 < 256; k0 += 16) {
#pragma unroll
        for (int L = 0; L < 2; L++) {
            int f = tid + L * 256;           // 0..511 float4 slots of a 128x16 tile
            int row = f >> 2;
            int c4 = (f & 3) << 2;
            float4 va = *(const float4*)(Ab + row * 256 + k0 + c4);
            As[c4 + 0][row] = va.x; As[c4 + 1][row] = va.y;
            As[c4 + 2][row] = va.z; As[c4 + 3][row] = va.w;
            float4 vb = *(const float4*)(Wb + row * 256 + k0 + c4);
            Bs[c4 + 0][row] = vb.x; Bs[c4 + 1][row] = vb.y;
            Bs[c4 + 2][row] = vb.z; Bs[c4 + 3][row] = vb.w;
        }
        __syncthreads();
#pragma unroll
        for (int kk = 0; kk < 16; kk++) {
            float4 a0 = *(const float4*)&As[kk][r * 8];
            float4 a1 = *(const float4*)&As[kk][r * 8 + 4];
            float4 b0 = *(const float4*)&Bs[kk][c * 8];
            float4 b1 = *(const float4*)&Bs[kk][c * 8 + 4];
            u64 bp0 = pack2(b0.x, b0.y), bp1 = pack2(b0.z, b0.w);
            u64 bp2 = pack2(b1.x, b1.y), bp3 = pack2(b1.z, b1.w);
            float av[8] = {a0.x, a0.y, a0.z, a0.w, a1.x, a1.y, a1.z, a1.w};
#pragma unroll
            for (int i = 0; i < 8; i++) {
                u64 ap = pack2b(av[i]);
                acc[i][0] = ffma2(ap, bp0, acc[i][0]);
                acc[i][1] = ffma2(ap, bp1, acc[i][1]);
                acc[i][2] = ffma2(ap, bp2, acc[i][2]);
                acc[i][3] = ffma2(ap, bp3, acc[i][3]);
            }
        }
        __syncthreads();
    }

    const int col0 = bn * 128 + c * 8;
    float bv[8];
#pragma unroll
    for (int j = 0; j < 8; j++) bv[j] = bias[col0 + j];

    if (MODE == 0) {
        // col -> (part, head, d). 8 cols always within one (part, head).
        const int part = col0 >> 8;
        const int h = (col0 >> 5) & 7;
        const int d0 = col0 & 31;
        const float scale = (part == 0) ? 0.17677669529663687f : 1.0f;
        float* dstb = (part == 0) ? g_q : ((part == 1) ? g_k : g_v);
#pragma unroll
        for (int i = 0; i < 8; i++) {
            int m = bm * 128 + r * 8 + i;
            int bidx = m / 49;
            int tok = m - bidx * 49;
            float* dst = dstb + ((size_t)(bidx * 8 + h) * 49 + tok) * 32 + d0;
            float o[8];
#pragma unroll
            for (int j2 = 0; j2 < 4; j2++) {
                float2 v = unpack2(acc[i][j2]);
                o[j2 * 2 + 0] = (v.x + bv[j2 * 2 + 0]) * scale;
                o[j2 * 2 + 1] = (v.y + bv[j2 * 2 + 1]) * scale;
            }
            *(float4*)(dst + 0) = make_float4(o[0], o[1], o[2], o[3]);
            *(float4*)(dst + 4) = make_float4(o[4], o[5], o[6], o[7]);
        }
    } else {
#pragma unroll
        for (int i = 0; i < 8; i++) {
            int m = bm * 128 + r * 8 + i;
            float* dst = out + (size_t)m * 256 + col0;
            float o[8];
#pragma unroll
            for (int j2 = 0; j2 < 4; j2++) {
                float2 v = unpack2(acc[i][j2]);
                o[j2 * 2 + 0] = v.x + bv[j2 * 2 + 0];
                o[j2 * 2 + 1] = v.y + bv[j2 * 2 + 1];
            }
            *(float4*)(dst + 0) = make_float4(o[0], o[1], o[2], o[3]);
            *(float4*)(dst + 4) = make_float4(o[4], o[5], o[6], o[7]);
        }
    }
}

// -------- fused window attention: one block per batch element --------
// Triple softmax combined into a single P = P0 + Pfg - Pbg, then one PV GEMM.
__global__ void __launch_bounds__(256) attn_kernel(const float* __restrict__ mask,
                                                   const float* __restrict__ fg,
                                                   const float* __restrict__ bg) {
    __shared__ __align__(16) float sQ[N_TOK * HDIM];
    __shared__ __align__(16) float sK[N_TOK * HDIM];
    __shared__ __align__(16) float sV[N_TOK * HDIM];
    __shared__ float sS[N_TOK * N_TOK];
    __shared__ float sFG[N_TOK * N_TOK];
    __shared__ float sBG[N_TOK * N_TOK];

    const int b = blockIdx.x;
    const int tid = threadIdx.x;
    const int warp = tid >> 5, lane = tid & 31;
    const int NN = N_TOK * N_TOK;   // 2401

    for (int i = tid; i < NN; i += 256) {
        sFG[i] = fg[(size_t)b * NN + i];
        sBG[i] = bg[(size_t)b * NN + i];
    }
    const float* mrow = mask + (size_t)(b & 63) * NN;

    for (int h = 0; h < NHEAD; h++) {
        size_t base = (size_t)(b * NHEAD + h) * (N_TOK * HDIM);
        for (int i = tid; i < (N_TOK * HDIM) / 4; i += 256) {
            ((float4*)sQ)[i] = ((const float4*)(g_q + base))[i];
            ((float4*)sK)[i] = ((const float4*)(g_k + base))[i];
            ((float4*)sV)[i] = ((const float4*)(g_v + base))[i];
        }
        __syncthreads();

        // S = Q K^T
        for (int idx = tid; idx < NN; idx += 256) {
            int i = idx / 49, j = idx - i * 49;
            const float4* qa = (const float4*)(sQ + i * 32);
            const float4* kb = (const float4*)(sK + j * 32);
            float acc = 0.f;
#pragma unroll
            for (int t = 0; t < 8; t++) {
                float4 a = qa[t], bb = kb[t];
                acc += a.x * bb.x + a.y * bb.y + a.z * bb.z + a.w * bb.w;
            }
            sS[idx] = acc;
        }
        __syncthreads();

        // triple softmax, one warp per row; P overwrites sS
        const float* biash = g_bias + h * NN;
        for (int row = warp; row < 49; row += 8) {
            int o0 = row * 49 + lane;
            int j1 = lane + 32;
            bool ok1 = (j1 < 49);
            float l0a = sS[o0] + mrow[o0] + biash[o0];
            float lfa = l0a + sFG[o0];
            float lba = l0a + sBG[o0];
            float l0b = -1e30f, lfb = -1e30f, lbb = -1e30f;
            if (ok1) {
                int o1 = row * 49 + j1;
                l0b = sS[o1] + mrow[o1] + biash[o1];
                lfb = l0b + sFG[o1];
                lbb = l0b + sBG[o1];
            }
            float m0 = fmaxf(l0a, l0b), mf = fmaxf(lfa, lfb), mb = fmaxf(lba, lbb);
#pragma unroll
            for (int o = 16; o; o >>= 1) {
                m0 = fmaxf(m0, __shfl_xor_sync(0xffffffffu, m0, o));
                mf = fmaxf(mf, __shfl_xor_sync(0xffffffffu, mf, o));
                mb = fmaxf(mb, __shfl_xor_sync(0xffffffffu, mb, o));
            }
            float e0a = __expf(l0a - m0), efa = __expf(lfa - mf), eba = __expf(lba - mb);
            float e0b = ok1 ? __expf(l0b - m0) : 0.f;
            float efb = ok1 ? __expf(lfb - mf) : 0.f;
            float ebb = ok1 ? __expf(lbb - mb) : 0.f;
            float s0 = e0a + e0b, sf = efa + efb, sb = eba + ebb;
#pragma unroll
            for (int o = 16; o; o >>= 1) {
                s0 += __shfl_xor_sync(0xffffffffu, s0, o);
                sf += __shfl_xor_sync(0xffffffffu, sf, o);
                sb += __shfl_xor_sync(0xffffffffu, sb, o);
            }
            float r0 = 1.f / s0, rf = 1.f / sf, rb = 1.f / sb;
            sS[o0] = e0a * r0 + efa * rf - eba * rb;
            if (ok1) sS[row * 49 + j1] = e0b * r0 + efb * rf - ebb * rb;
        }
        __syncthreads();

        // O = P @ V  -> g_attn_out[b][tok][h*32+d]
        for (int idx = tid; idx < N_TOK * HDIM; idx += 256) {
            int i = idx >> 5, d = idx & 31;
            const float* prow = sS + i * 49;
            const float* vcol = sV + d;
            float acc = 0.f;
#pragma unroll
            for (int j = 0; j < 49; j++) acc += prow[j] * vcol[j * 32];
            g_attn_out[((size_t)b * 49 + i) * 256 + h * 32 + d] = acc;
        }
        __syncthreads();
    }
}

extern "C" void kernel_launch(void* const* d_in, const int* in_sizes, int n_in,
                              void* d_out, int out_size) {
    const float* x      = (const float*)d_in[0];
    const float* mask   = (const float*)d_in[1];
    const float* fg     = (const float*)d_in[2];
    const float* bg     = (const float*)d_in[3];
    const float* qkv_w  = (const float*)d_in[4];
    const float* qkv_b  = (const float*)d_in[5];
    const float* proj_w = (const float*)d_in[6];
    const float* proj_b = (const float*)d_in[7];
    const float* table  = (const float*)d_in[8];
    float* out = (float*)d_out;

    bias_kernel<<<(NHEAD * N_TOK * N_TOK + 255) / 256, 256>>>(table);
    gemm_kernel<0><<<dim3(M_ROWS / 128, 768 / 128), 256>>>(x, qkv_w, qkv_b, nullptr);
    attn_kernel<<<B_TOT, 256>>>(mask, fg, bg);
    gemm_kernel<1><<<dim3(M_ROWS / 128, 256 / 128), 256>>>(nullptr, proj_w, proj_b, out);
}

// round 2
// speedup vs baseline: 1.7436x; 1.7436x over previous
#include <cuda_runtime.h>
#include <cstdint>
#include <cstddef>

typedef unsigned long long u64;

#define B_TOT 2048
#define N_TOK 49
#define CDIM  256
#define NHEAD 8
#define HDIM  32
#define M_ROWS (B_TOT * N_TOK)      // 100352
#define NN 2401                      // 49*49

// -------- scratch (device globals: no allocation allowed) --------
__device__ __align__(16) float g_q[(size_t)B_TOT * NHEAD * N_TOK * HDIM];
__device__ __align__(16) float g_k[(size_t)B_TOT * NHEAD * N_TOK * HDIM];
__device__ __align__(16) float g_v[(size_t)B_TOT * NHEAD * N_TOK * HDIM];
__device__ __align__(16) float g_attn_out[(size_t)M_ROWS * CDIM];
__device__ float g_emb[64 * NHEAD * NN];   // exp(mask[w] + rel_pos_bias[h])

// -------- packed-fp32 helpers (fma.rn.f32x2, sm_100+) --------
__device__ __forceinline__ u64 pack2(float x, float y) {
    u64 r; asm("mov.b64 %0,{%1,%2};" : "=l"(r) : "f"(x), "f"(y)); return r;
}
__device__ __forceinline__ u64 pack2b(float x) {
    u64 r; asm("mov.b64 %0,{%1,%1};" : "=l"(r) : "f"(x)); return r;
}
__device__ __forceinline__ u64 ffma2(u64 a, u64 b, u64 c) {
    u64 d; asm("fma.rn.f32x2 %0,%1,%2,%3;" : "=l"(d) : "l"(a), "l"(b), "l"(c)); return d;
}
__device__ __forceinline__ float2 unpack2(u64 v) {
    float lo, hi; asm("mov.b64 {%0,%1},%2;" : "=f"(lo), "=f"(hi) : "l"(v));
    return make_float2(lo, hi);
}

// -------- precompute exp(mask[w][i][j] + bias[h][i][j]) --------
__global__ void emb_kernel(const float* __restrict__ table,
                           const float* __restrict__ mask) {
    int t = blockIdx.x * blockDim.x + threadIdx.x;
    if (t >= 64 * NHEAD * NN) return;
    int w   = t / (NHEAD * NN);
    int rem = t - w * (NHEAD * NN);
    int h   = rem / NN;
    int ij  = rem - h * NN;
    int i = ij / 49, j = ij - i * 49;
    int ri = i / 7, ci = i - ri * 7;
    int rj = j / 7, cj = j - rj * 7;
    int idx = (ri - rj + 6) * 13 + (ci - cj + 6);
    g_emb[t] = __expf(mask[w * NN + ij] + table[idx * NHEAD + h]);
}

// -------- SGEMM: C[M][Ncols] = A[M][256] @ W[Ncols][256]^T + bias --------
// BM=BN=128, BK=8, double-buffered smem, 256 threads, 8x8 microtile, ffma2.
// grid = (bn, bm) so adjacent CTAs share the same A tile via L2.
template<int MODE>
__global__ void __launch_bounds__(256, 2) gemm_kernel(const float* __restrict__ A_in,
                                                      const float* __restrict__ W,
                                                      const float* __restrict__ bias,
                                                      float* __restrict__ out) {
    __shared__ __align__(16) float As[2][8][128];
    __shared__ __align__(16) float Bs[2][8][128];

    const float* A = (MODE == 0) ? A_in : g_attn_out;
    const int tid = threadIdx.x;
    const int bn = blockIdx.x, bm = blockIdx.y;
    const int r = tid >> 4;      // rows r*8 .. r*8+7
    const int c = tid & 15;      // cols c*8 .. c*8+7
    const int lrow = tid >> 1;   // 0..127
    const int lc4 = (tid & 1) << 2;

    const float* Aptr = A + (size_t)(bm * 128 + lrow) * 256 + lc4;
    const float* Wptr = W + (size_t)(bn * 128 + lrow) * 256 + lc4;

    u64 acc[8][4];
#pragma unroll
    for (int i = 0; i < 8; i++)
#pragma unroll
        for (int j = 0; j < 4; j++) acc[i][j] = 0ull;

    float4 ra = *(const float4*)(Aptr);
    float4 rb = *(const float4*)(Wptr);
    As[0][lc4 + 0][lrow] = ra.x; As[0][lc4 + 1][lrow] = ra.y;
    As[0][lc4 + 2][lrow] = ra.z; As[0][lc4 + 3][lrow] = ra.w;
    Bs[0][lc4 + 0][lrow] = rb.x; Bs[0][lc4 + 1][lrow] = rb.y;
    Bs[0][lc4 + 2][lrow] = rb.z; Bs[0][lc4 + 3][lrow] = rb.w;
    __syncthreads();

    for (int t = 0; t < 32; t++) {
        const int buf = t & 1;
        if (t < 31) {
            ra = *(const float4*)(Aptr + (t + 1) * 8);
            rb = *(const float4*)(Wptr + (t + 1) * 8);
        }
#pragma unroll
        for (int kk = 0; kk < 8; kk++) {
            float4 a0 = *(const float4*)&As[buf][kk][r * 8];
            float4 a1 = *(const float4*)&As[buf][kk][r * 8 + 4];
            float4 b0 = *(const float4*)&Bs[buf][kk][c * 8];
            float4 b1 = *(const float4*)&Bs[buf][kk][c * 8 + 4];
            u64 bp0 = pack2(b0.x, b0.y), bp1 = pack2(b0.z, b0.w);
            u64 bp2 = pack2(b1.x, b1.y), bp3 = pack2(b1.z, b1.w);
            float av[8] = {a0.x, a0.y, a0.z, a0.w, a1.x, a1.y, a1.z, a1.w};
#pragma unroll
            for (int i = 0; i < 8; i++) {
                u64 ap = pack2b(av[i]);
                acc[i][0] = ffma2(ap, bp0, acc[i][0]);
                acc[i][1] = ffma2(ap, bp1, acc[i][1]);
                acc[i][2] = ffma2(ap, bp2, acc[i][2]);
                acc[i][3] = ffma2(ap, bp3, acc[i][3]);
            }
        }
        if (t < 31) {
            const int nb = buf ^ 1;
            As[nb][lc4 + 0][lrow] = ra.x; As[nb][lc4 + 1][lrow] = ra.y;
            As[nb][lc4 + 2][lrow] = ra.z; As[nb][lc4 + 3][lrow] = ra.w;
            Bs[nb][lc4 + 0][lrow] = rb.x; Bs[nb][lc4 + 1][lrow] = rb.y;
            Bs[nb][lc4 + 2][lrow] = rb.z; Bs[nb][lc4 + 3][lrow] = rb.w;
            __syncthreads();
        }
    }

    const int col0 = bn * 128 + c * 8;
    float bv[8];
#pragma unroll
    for (int j = 0; j < 8; j++) bv[j] = bias[col0 + j];

    if (MODE == 0) {
        const int part = col0 >> 8;
        const int h = (col0 >> 5) & 7;
        const int d0 = col0 & 31;
        const float scale = (part == 0) ? 0.17677669529663687f : 1.0f;
        float* dstb = (part == 0) ? g_q : ((part == 1) ? g_k : g_v);
#pragma unroll
        for (int i = 0; i < 8; i++) {
            int m = bm * 128 + r * 8 + i;
            int bidx = m / 49;
            int tok = m - bidx * 49;
            float* dst = dstb + ((size_t)(bidx * 8 + h) * 49 + tok) * 32 + d0;
            float o[8];
#pragma unroll
            for (int j2 = 0; j2 < 4; j2++) {
                float2 v = unpack2(acc[i][j2]);
                o[j2 * 2 + 0] = (v.x + bv[j2 * 2 + 0]) * scale;
                o[j2 * 2 + 1] = (v.y + bv[j2 * 2 + 1]) * scale;
            }
            *(float4*)(dst + 0) = make_float4(o[0], o[1], o[2], o[3]);
            *(float4*)(dst + 4) = make_float4(o[4], o[5], o[6], o[7]);
        }
    } else {
#pragma unroll
        for (int i = 0; i < 8; i++) {
            int m = bm * 128 + r * 8 + i;
            float* dst = out + (size_t)m * 256 + col0;
            float o[8];
#pragma unroll
            for (int j2 = 0; j2 < 4; j2++) {
                float2 v = unpack2(acc[i][j2]);
                o[j2 * 2 + 0] = v.x + bv[j2 * 2 + 0];
                o[j2 * 2 + 1] = v.y + bv[j2 * 2 + 1];
            }
            *(float4*)(dst + 0) = make_float4(o[0], o[1], o[2], o[3]);
            *(float4*)(dst + 4) = make_float4(o[4], o[5], o[6], o[7]);
        }
    }
}

// -------- fused window attention (block = one batch element) --------
// E0 = exp(S)*exp(mask+bias);  P = E0*(r0 + rf*Efg - rb*Ebg); single PV GEMM.
__global__ void __launch_bounds__(256) attn_kernel(const float* __restrict__ fg,
                                                   const float* __restrict__ bg) {
    __shared__ __align__(16) float sQ[50 * 32];       // row 49 zero pad
    __shared__ __align__(16) float sKt[32 * 52];      // [k][j], cols 49..51 pad
    __shared__ __align__(16) float sV[49 * 32];
    __shared__ __align__(16) float sE[50 * 52];       // E0 then P, row 49 pad
    __shared__ float sFG[NN];                         // exp(fg)
    __shared__ float sBG[NN];                         // exp(bg)

    const int b = blockIdx.x;
    const int tid = threadIdx.x;
    const int warp = tid >> 5, lane = tid & 31;

    for (int i = tid; i < NN; i += 256) {
        sFG[i] = __expf(fg[(size_t)b * NN + i]);
        sBG[i] = __expf(bg[(size_t)b * NN + i]);
    }
    if (tid < 32) sQ[49 * 32 + tid] = 0.f;            // zero pad row of Q
    if (tid < 96) {                                    // zero pad cols of Kt
        int k = tid / 3, j = 49 + tid % 3;
        sKt[k * 52 + j] = 0.f;
    }
    __syncthreads();

    for (int h = 0; h < NHEAD; h++) {
        const size_t base = (size_t)(b * NHEAD + h) * (N_TOK * HDIM);
        for (int f = tid; f < 392; f += 256) {
            ((float4*)sQ)[f] = ((const float4*)(g_q + base))[f];
            ((float4*)sV)[f] = ((const float4*)(g_v + base))[f];
            float4 kv = ((const float4*)(g_k + base))[f];
            int j = f >> 3, k4 = (f & 7) << 2;
            sKt[(k4 + 0) * 52 + j] = kv.x; sKt[(k4 + 1) * 52 + j] = kv.y;
            sKt[(k4 + 2) * 52 + j] = kv.z; sKt[(k4 + 3) * 52 + j] = kv.w;
        }
        __syncthreads();

        // ---- S = Q K^T, E0 = exp(S)*emb, 2x4 register tiles ----
        const float* embh = g_emb + (size_t)((b & 63) * NHEAD + h) * NN;
        for (int job = tid; job < 325; job += 256) {
            int iP = job / 13, jq = job - iP * 13;
            int i0 = iP * 2, j0 = jq * 4;
            u64 a00 = 0, a01 = 0, a10 = 0, a11 = 0;
            const float* q0 = sQ + i0 * 32;
            const float* kt = sKt + j0;
#pragma unroll 8
            for (int k = 0; k < 32; k++) {
                float4 kv = *(const float4*)(kt + k * 52);
                u64 k0p = pack2(kv.x, kv.y), k1p = pack2(kv.z, kv.w);
                u64 qpa = pack2b(q0[k]);
                u64 qpb = pack2b(q0[32 + k]);
                a00 = ffma2(qpa, k0p, a00); a01 = ffma2(qpa, k1p, a01);
                a10 = ffma2(qpb, k0p, a10); a11 = ffma2(qpb, k1p, a11);
            }
            {
                float* er = sE + i0 * 52;
                const float* m0 = embh + i0 * 49;
                float2 v0 = unpack2(a00), v1 = unpack2(a01);
                er[j0] = __expf(v0.x) * m0[j0];
                if (j0 + 1 < 49) er[j0 + 1] = __expf(v0.y) * m0[j0 + 1];
                if (j0 + 2 < 49) er[j0 + 2] = __expf(v1.x) * m0[j0 + 2];
                if (j0 + 3 < 49) er[j0 + 3] = __expf(v1.y) * m0[j0 + 3];
            }
            if (i0 + 1 < 49) {
                float* er = sE + (i0 + 1) * 52;
                const float* m1 = embh + (i0 + 1) * 49;
                float2 v0 = unpack2(a10), v1 = unpack2(a11);
                er[j0] = __expf(v0.x) * m1[j0];
                if (j0 + 1 < 49) er[j0 + 1] = __expf(v0.y) * m1[j0 + 1];
                if (j0 + 2 < 49) er[j0 + 2] = __expf(v1.x) * m1[j0 + 2];
                if (j0 + 3 < 49) er[j0 + 3] = __expf(v1.y) * m1[j0 + 3];
            }
        }
        __syncthreads();

        // ---- row sums + combined P (warp per row) ----
        for (int row = warp; row < 49; row += 8) {
            float* er = sE + row * 52;
            const float* fgr = sFG + row * 49;
            const float* bgr = sBG + row * 49;
            bool ok = lane < 17;
            float e0  = er[lane];
            float fga = fgr[lane], bga = bgr[lane];
            float e0b = ok ? er[lane + 32] : 0.f;
            float fgb = ok ? fgr[lane + 32] : 0.f;
            float bgb = ok ? bgr[lane + 32] : 0.f;
            float s0 = e0 + e0b;
            float sf = e0 * fga + e0b * fgb;
            float sb = e0 * bga + e0b * bgb;
#pragma unroll
            for (int o = 16; o; o >>= 1) {
                s0 += __shfl_xor_sync(0xffffffffu, s0, o);
                sf += __shfl_xor_sync(0xffffffffu, sf, o);
                sb += __shfl_xor_sync(0xffffffffu, sb, o);
            }
            float r0 = 1.f / s0, rf = 1.f / sf, rb = 1.f / sb;
            er[lane] = e0 * (r0 + rf * fga - rb * bga);
            if (ok) er[lane + 32] = e0b * (r0 + rf * fgb - rb * bgb);
        }
        __syncthreads();

        // ---- O = P @ V (2x4 register tiles) ----
        if (tid < 200) {
            int iP = tid >> 3, dq = tid & 7;
            int i0 = iP * 2, d0 = dq * 4;
            u64 a00 = 0, a01 = 0, a10 = 0, a11 = 0;
            const float* p0 = sE + i0 * 52;
            const float* p1 = p0 + 52;
            const float* vp = sV + d0;
#pragma unroll 7
            for (int j = 0; j < 49; j++) {
                float4 vv = *(const float4*)(vp + j * 32);
                u64 v0 = pack2(vv.x, vv.y), v1 = pack2(vv.z, vv.w);
                u64 pa = pack2b(p0[j]);
                u64 pb = pack2b(p1[j]);
                a00 = ffma2(pa, v0, a00); a01 = ffma2(pa, v1, a01);
                a10 = ffma2(pb, v0, a10); a11 = ffma2(pb, v1, a11);
            }
            float* o0 = g_attn_out + ((size_t)(b * 49 + i0)) * 256 + h * 32 + d0;
            float2 x0 = unpack2(a00), x1 = unpack2(a01);
            *(float4*)o0 = make_float4(x0.x, x0.y, x1.x, x1.y);
            if (i0 + 1 < 49) {
                float2 y0 = unpack2(a10), y1 = unpack2(a11);
                *(float4*)(o0 + 256) = make_float4(y0.x, y0.y, y1.x, y1.y);
            }
        }
        __syncthreads();
    }
}

extern "C" void kernel_launch(void* const* d_in, const int* in_sizes, int n_in,
                              void* d_out, int out_size) {
    const float* x      = (const float*)d_in[0];
    const float* mask   = (const float*)d_in[1];
    const float* fg     = (const float*)d_in[2];
    const float* bg     = (const float*)d_in[3];
    const float* qkv_w  = (const float*)d_in[4];
    const float* qkv_b  = (const float*)d_in[5];
    const float* proj_w = (const float*)d_in[6];
    const float* proj_b = (const float*)d_in[7];
    const float* table  = (const float*)d_in[8];
    float* out = (float*)d_out;

    emb_kernel<<<(64 * NHEAD * NN + 255) / 256, 256>>>(table, mask);
    gemm_kernel<0><<<dim3(6, 784), 256>>>(x, qkv_w, qkv_b, nullptr);
    attn_kernel<<<B_TOT, 256>>>(fg, bg);
    gemm_kernel<1><<<dim3(2, 784), 256>>>(nullptr, proj_w, proj_b, out);
}

// round 4
// speedup vs baseline: 2.9364x; 1.6841x over previous
#include <cuda_runtime.h>
#include <cuda_fp16.h>
#include <cstdint>
#include <cstddef>

typedef unsigned long long u64;
typedef unsigned int u32;

#define B_TOT 2048
#define N_TOK 49
#define CDIM  256
#define NHEAD 8
#define HDIM  32
#define M_ROWS (B_TOT * N_TOK)      // 100352
#define NN 2401                      // 49*49

// -------- scratch (device globals: no allocation allowed) --------
__device__ __align__(16) float g_q[(size_t)B_TOT * NHEAD * N_TOK * HDIM];
__device__ __align__(16) float g_k[(size_t)B_TOT * NHEAD * N_TOK * HDIM];
__device__ __align__(16) float g_v[(size_t)B_TOT * NHEAD * N_TOK * HDIM];
__device__ __align__(16) __half g_xh[(size_t)M_ROWS * 512];    // x hi|lo fp16
__device__ __align__(16) __half g_ah[(size_t)M_ROWS * 512];    // attn-out hi|lo
__device__ __align__(16) __half g_wqkv[768 * 512];
__device__ __align__(16) __half g_wproj[256 * 512];
__device__ float g_emb[64 * NHEAD * NN];   // exp(mask[w] + rel_pos_bias[h])

// -------- packed-fp32 helpers (fma.rn.f32x2) --------
__device__ __forceinline__ u64 pack2(float x, float y) {
    u64 r; asm("mov.b64 %0,{%1,%2};" : "=l"(r) : "f"(x), "f"(y)); return r;
}
__device__ __forceinline__ u64 pack2b(float x) {
    u64 r; asm("mov.b64 %0,{%1,%1};" : "=l"(r) : "f"(x)); return r;
}
__device__ __forceinline__ u64 ffma2(u64 a, u64 b, u64 c) {
    u64 d; asm("fma.rn.f32x2 %0,%1,%2,%3;" : "=l"(d) : "l"(a), "l"(b), "l"(c)); return d;
}
__device__ __forceinline__ float2 unpack2(u64 v) {
    float lo, hi; asm("mov.b64 {%0,%1},%2;" : "=f"(lo), "=f"(hi) : "l"(v));
    return make_float2(lo, hi);
}

// -------- smem / async-copy / mma helpers (all standard PTX) --------
__device__ __forceinline__ u32 smem_u32(const void* p) {
    u32 a; asm("{ .reg .u64 t; cvta.to.shared.u64 t,%1; cvt.u32.u64 %0,t; }" : "=r"(a) : "l"(p));
    return a;
}
__device__ __forceinline__ void cp16(u32 dst, const void* src) {
    asm volatile("cp.async.cg.shared.global [%0], [%1], 16;" :: "r"(dst), "l"(src));
}
__device__ __forceinline__ u32 lds32(u32 addr) {
    u32 v; asm volatile("ld.shared.b32 %0,[%1];" : "=r"(v) : "r"(addr)); return v;
}
__device__ __forceinline__ void hmma16816(float* c, const u32* a, const u32* b) {
    asm volatile(
        "mma.sync.aligned.m16n8k16.row.col.f32.f16.f16.f32 "
        "{%0,%1,%2,%3},{%4,%5,%6,%7},{%8,%9},{%0,%1,%2,%3};"
        : "+f"(c[0]), "+f"(c[1]), "+f"(c[2]), "+f"(c[3])
        : "r"(a[0]), "r"(a[1]), "r"(a[2]), "r"(a[3]), "r"(b[0]), "r"(b[1]));
}

// -------- fp32 -> (hi|lo) fp16: [R,256] f32 -> [R,512] half --------
__global__ void conv_h(const float* __restrict__ src, __half* __restrict__ dst, int rows) {
    int t = blockIdx.x * blockDim.x + threadIdx.x;
    if (t >= rows * 64) return;
    int m = t >> 6, k4 = (t & 63) << 2;
    float4 v = *(const float4*)(src + (size_t)m * 256 + k4);
    __half h0 = __float2half_rn(v.x), h1 = __float2half_rn(v.y);
    __half h2 = __float2half_rn(v.z), h3 = __float2half_rn(v.w);
    __half2 hh, ll;
    __half* dh = dst + (size_t)m * 512 + k4;
    hh.x = h0; hh.y = h1; *(__half2*)(dh) = hh;
    hh.x = h2; hh.y = h3; *(__half2*)(dh + 2) = hh;
    ll.x = __float2half_rn(v.x - __half2float(h0));
    ll.y = __float2half_rn(v.y - __half2float(h1));
    *(__half2*)(dh + 256) = ll;
    ll.x = __float2half_rn(v.z - __half2float(h2));
    ll.y = __float2half_rn(v.w - __half2float(h3));
    *(__half2*)(dh + 258) = ll;
}

// -------- precompute exp(mask[w][i][j] + bias[h][i][j]) --------
__global__ void emb_kernel(const float* __restrict__ table,
                           const float* __restrict__ mask) {
    int t = blockIdx.x * blockDim.x + threadIdx.x;
    if (t >= 64 * NHEAD * NN) return;
    int w   = t / (NHEAD * NN);
    int rem = t - w * (NHEAD * NN);
    int h   = rem / NN;
    int ij  = rem - h * NN;
    int i = ij / 49, j = ij - i * 49;
    int ri = i / 7, ci = i - ri * 7;
    int rj = j / 7, cj = j - rj * 7;
    int idx = (ri - rj + 6) * 13 + (ci - cj + 6);
    g_emb[t] = __expf(mask[w * NN + ij] + table[idx * NHEAD + h]);
}

// -------- HMMA GEMM: C[M,Ncols] = A[M,256] @ W[Ncols,256]^T + bias --------
// A,W as [rows,512] fp16 (hi 0..255 | lo 256..511). Split product:
// D += Ah*Bh + Ah*Bl + Al*Bh (fp32 accum). CTA 128x128, warp tile 64x32.
// K sliced x8 (32 cols), 4 tiles (Ah,Al,Bh,Bl) double-buffered via cp.async.
#define TSTRIDE 112                 // bytes per smem row (56 halfs)
#define TILE_B  (128 * TSTRIDE)     // 14336
#define STAGE_B (4 * TILE_B)        // 57344
#define GEMM_SMEM (2 * STAGE_B)     // 114688

template<int MODE>
__global__ void __launch_bounds__(256) hgemm(const __half* __restrict__ Ah_,
                                             const __half* __restrict__ Wh_,
                                             const float* __restrict__ bias,
                                             float* __restrict__ out) {
    extern __shared__ char smem[];
    const u32 sb = smem_u32(smem);
    const int tid = threadIdx.x;
    const int wid = tid >> 5, lane = tid & 31;
    const int g = lane >> 2, t = lane & 3;
    const int wm = wid >> 2, wn = wid & 3;          // warp grid 2m x 4n
    const int bn = blockIdx.x, bm = blockIdx.y;

    const char* Asrc = (const char*)(Ah_ + (size_t)(bm * 128) * 512);
    const char* Wsrc = (const char*)(Wh_ + (size_t)(bn * 128) * 512);

    float acc[4][4][4];
#pragma unroll
    for (int i = 0; i < 4; i++)
#pragma unroll
        for (int j = 0; j < 4; j++)
#pragma unroll
            for (int q = 0; q < 4; q++) acc[i][j][q] = 0.f;

    const int r_ld = tid >> 2, c4 = tid & 3;        // 64 rows per 256-thread pass

    // issue cp.async for slice s into stage s&1
    auto issue = [&](int s) {
        const u32 dbase = sb + (s & 1) * STAGE_B;
        const size_t cb = (size_t)s * 64 + c4 * 16;  // byte col offset (hi)
#pragma unroll
        for (int i = 0; i < 2; i++) {
            const int r = r_ld + i * 64;
            const u32 d = dbase + r * TSTRIDE + c4 * 16;
            const size_t go = (size_t)r * 1024 + cb;
            cp16(d + 0 * TILE_B, Asrc + go);
            cp16(d + 1 * TILE_B, Asrc + go + 512);
            cp16(d + 2 * TILE_B, Wsrc + go);
            cp16(d + 3 * TILE_B, Wsrc + go + 512);
        }
        asm volatile("cp.async.commit_group;" ::: "memory");
    };

    issue(0);
    for (int s = 0; s < 8; s++) {
        if (s < 7) {
            issue(s + 1);
            asm volatile("cp.async.wait_group 1;" ::: "memory");
        } else {
            asm volatile("cp.async.wait_group 0;" ::: "memory");
        }
        __syncthreads();

        const u32 stb = sb + (s & 1) * STAGE_B;
        const u32 A0 = stb, A1 = stb + TILE_B, B0 = stb + 2 * TILE_B, B1 = stb + 3 * TILE_B;
#pragma unroll
        for (int s2 = 0; s2 < 2; s2++) {
            const u32 w0 = (s2 * 8 + t) * 4;        // byte offset of k-word
            u32 ah[4][4], al[4][4], bh[4][2], bl[4][2];
#pragma unroll
            for (int mt = 0; mt < 4; mt++) {
                const u32 r0 = (wm * 64 + mt * 16 + g) * TSTRIDE + w0;
                const u32 r1 = r0 + 8 * TSTRIDE;
                ah[mt][0] = lds32(A0 + r0);      ah[mt][1] = lds32(A0 + r1);
                ah[mt][2] = lds32(A0 + r0 + 16); ah[mt][3] = lds32(A0 + r1 + 16);
                al[mt][0] = lds32(A1 + r0);      al[mt][1] = lds32(A1 + r1);
                al[mt][2] = lds32(A1 + r0 + 16); al[mt][3] = lds32(A1 + r1 + 16);
            }
#pragma unroll
            for (int nt = 0; nt < 4; nt++) {
                const u32 rb = (wn * 32 + nt * 8 + g) * TSTRIDE + w0;
                bh[nt][0] = lds32(B0 + rb); bh[nt][1] = lds32(B0 + rb + 16);
                bl[nt][0] = lds32(B1 + rb); bl[nt][1] = lds32(B1 + rb + 16);
            }
#pragma unroll
            for (int mt = 0; mt < 4; mt++)
#pragma unroll
                for (int nt = 0; nt < 4; nt++) {
                    hmma16816(acc[mt][nt], ah[mt], bh[nt]);
                    hmma16816(acc[mt][nt], ah[mt], bl[nt]);
                    hmma16816(acc[mt][nt], al[mt], bh[nt]);
                }
        }
        __syncthreads();
    }

    // ---- epilogue: direct gmem float2 stores ----
#pragma unroll
    for (int nt = 0; nt < 4; nt++) {
        const int col0 = bn * 128 + wn * 32 + nt * 8 + t * 2;
        const float b0 = bias[col0], b1 = bias[col0 + 1];
        if (MODE == 0) {
            const int part = col0 >> 8;
            const int h = (col0 >> 5) & 7;
            const int d0 = col0 & 31;
            const float scale = (part == 0) ? 0.17677669529663687f : 1.0f;
            float* dstb = (part == 0) ? g_q : ((part == 1) ? g_k : g_v);
#pragma unroll
            for (int mt = 0; mt < 4; mt++) {
                const float* c = acc[mt][nt];
#pragma unroll
                for (int rr = 0; rr < 2; rr++) {
                    const int m = bm * 128 + wm * 64 + mt * 16 + g + rr * 8;
                    const int bidx = m / 49, tok = m - bidx * 49;
                    float* dst = dstb + ((size_t)(bidx * 8 + h) * 49 + tok) * 32 + d0;
                    float2 v;
                    v.x = (c[rr * 2 + 0] + b0) * scale;
                    v.y = (c[rr * 2 + 1] + b1) * scale;
                    *(float2*)dst = v;
                }
            }
        } else {
#pragma unroll
            for (int mt = 0; mt < 4; mt++) {
                const float* c = acc[mt][nt];
#pragma unroll
                for (int rr = 0; rr < 2; rr++) {
                    const int m = bm * 128 + wm * 64 + mt * 16 + g + rr * 8;
                    float2 v;
                    v.x = c[rr * 2 + 0] + b0;
                    v.y = c[rr * 2 + 1] + b1;
                    *(float2*)(out + (size_t)m * 256 + col0) = v;
                }
            }
        }
    }
}

// -------- fused window attention (block = one batch element) --------
// E0 = exp(S)*exp(mask+bias);  P = E0*(r0 + rf*Efg - rb*Ebg); single PV GEMM.
// Epilogue writes fp16 hi|lo directly for the proj GEMM.
__global__ void __launch_bounds__(256) attn_kernel(const float* __restrict__ fg,
                                                   const float* __restrict__ bg) {
    __shared__ __align__(16) float sQ[50 * 32];
    __shared__ __align__(16) float sKt[32 * 52];
    __shared__ __align__(16) float sV[49 * 32];
    __shared__ __align__(16) float sE[50 * 52];
    __shared__ float sFG[NN];
    __shared__ float sBG[NN];

    const int b = blockIdx.x;
    const int tid = threadIdx.x;
    const int warp = tid >> 5, lane = tid & 31;

    for (int i = tid; i < NN; i += 256) {
        sFG[i] = __expf(fg[(size_t)b * NN + i]);
        sBG[i] = __expf(bg[(size_t)b * NN + i]);
    }
    if (tid < 32) sQ[49 * 32 + tid] = 0.f;
    if (tid < 96) {
        int k = tid / 3, j = 49 + tid % 3;
        sKt[k * 52 + j] = 0.f;
    }
    __syncthreads();

    for (int h = 0; h < NHEAD; h++) {
        const size_t base = (size_t)(b * NHEAD + h) * (N_TOK * HDIM);
        for (int f = tid; f < 392; f += 256) {
            ((float4*)sQ)[f] = ((const float4*)(g_q + base))[f];
            ((float4*)sV)[f] = ((const float4*)(g_v + base))[f];
            float4 kv = ((const float4*)(g_k + base))[f];
            int j = f >> 3, k4 = (f & 7) << 2;
            sKt[(k4 + 0) * 52 + j] = kv.x; sKt[(k4 + 1) * 52 + j] = kv.y;
            sKt[(k4 + 2) * 52 + j] = kv.z; sKt[(k4 + 3) * 52 + j] = kv.w;
        }
        __syncthreads();

        const float* embh = g_emb + (size_t)((b & 63) * NHEAD + h) * NN;
        for (int job = tid; job < 325; job += 256) {
            int iP = job / 13, jq = job - iP * 13;
            int i0 = iP * 2, j0 = jq * 4;
            u64 a00 = 0, a01 = 0, a10 = 0, a11 = 0;
            const float* q0 = sQ + i0 * 32;
            const float* kt = sKt + j0;
#pragma unroll 8
            for (int k = 0; k < 32; k++) {
                float4 kv = *(const float4*)(kt + k * 52);
                u64 k0p = pack2(kv.x, kv.y), k1p = pack2(kv.z, kv.w);
                u64 qpa = pack2b(q0[k]);
                u64 qpb = pack2b(q0[32 + k]);
                a00 = ffma2(qpa, k0p, a00); a01 = ffma2(qpa, k1p, a01);
                a10 = ffma2(qpb, k0p, a10); a11 = ffma2(qpb, k1p, a11);
            }
            {
                float* er = sE + i0 * 52;
                const float* m0 = embh + i0 * 49;
                float2 v0 = unpack2(a00), v1 = unpack2(a01);
                er[j0] = __expf(v0.x) * m0[j0];
                if (j0 + 1 < 49) er[j0 + 1] = __expf(v0.y) * m0[j0 + 1];
                if (j0 + 2 < 49) er[j0 + 2] = __expf(v1.x) * m0[j0 + 2];
                if (j0 + 3 < 49) er[j0 + 3] = __expf(v1.y) * m0[j0 + 3];
            }
            if (i0 + 1 < 49) {
                float* er = sE + (i0 + 1) * 52;
                const float* m1 = embh + (i0 + 1) * 49;
                float2 v0 = unpack2(a10), v1 = unpack2(a11);
                er[j0] = __expf(v0.x) * m1[j0];
                if (j0 + 1 < 49) er[j0 + 1] = __expf(v0.y) * m1[j0 + 1];
                if (j0 + 2 < 49) er[j0 + 2] = __expf(v1.x) * m1[j0 + 2];
                if (j0 + 3 < 49) er[j0 + 3] = __expf(v1.y) * m1[j0 + 3];
            }
        }
        __syncthreads();

        for (int row = warp; row < 49; row += 8) {
            float* er = sE + row * 52;
            const float* fgr = sFG + row * 49;
            const float* bgr = sBG + row * 49;
            bool ok = lane < 17;
            float e0  = er[lane];
            float fga = fgr[lane], bga = bgr[lane];
            float e0b = ok ? er[lane + 32] : 0.f;
            float fgb = ok ? fgr[lane + 32] : 0.f;
            float bgb = ok ? bgr[lane + 32] : 0.f;
            float s0 = e0 + e0b;
            float sf = e0 * fga + e0b * fgb;
            float sb2 = e0 * bga + e0b * bgb;
#pragma unroll
            for (int o = 16; o; o >>= 1) {
                s0  += __shfl_xor_sync(0xffffffffu, s0, o);
                sf  += __shfl_xor_sync(0xffffffffu, sf, o);
                sb2 += __shfl_xor_sync(0xffffffffu, sb2, o);
            }
            float r0 = 1.f / s0, rf = 1.f / sf, rb = 1.f / sb2;
            er[lane] = e0 * (r0 + rf * fga - rb * bga);
            if (ok) er[lane + 32] = e0b * (r0 + rf * fgb - rb * bgb);
        }
        __syncthreads();

        if (tid < 200) {
            int iP = tid >> 3, dq = tid & 7;
            int i0 = iP * 2, d0 = dq * 4;
            u64 a00 = 0, a01 = 0, a10 = 0, a11 = 0;
            const float* p0 = sE + i0 * 52;
            const float* p1 = p0 + 52;
            const float* vp = sV + d0;
#pragma unroll 7
            for (int j = 0; j < 49; j++) {
                float4 vv = *(const float4*)(vp + j * 32);
                u64 v0 = pack2(vv.x, vv.y), v1 = pack2(vv.z, vv.w);
                u64 pa = pack2b(p0[j]);
                u64 pb = pack2b(p1[j]);
                a00 = ffma2(pa, v0, a00); a01 = ffma2(pa, v1, a01);
                a10 = ffma2(pb, v0, a10); a11 = ffma2(pb, v1, a11);
            }
            __half* o0 = g_ah + ((size_t)(b * 49 + i0)) * 512 + h * 32 + d0;
            {
                float2 x0 = unpack2(a00), x1 = unpack2(a01);
                float vv[4] = {x0.x, x0.y, x1.x, x1.y};
                __half h0 = __float2half_rn(vv[0]), h1 = __float2half_rn(vv[1]);
                __half h2 = __float2half_rn(vv[2]), h3 = __float2half_rn(vv[3]);
                __half2 hh, ll;
                hh.x = h0; hh.y = h1; *(__half2*)(o0) = hh;
                hh.x = h2; hh.y = h3; *(__half2*)(o0 + 2) = hh;
                ll.x = __float2half_rn(vv[0] - __half2float(h0));
                ll.y = __float2half_rn(vv[1] - __half2float(h1));
                *(__half2*)(o0 + 256) = ll;
                ll.x = __float2half_rn(vv[2] - __half2float(h2));
                ll.y = __float2half_rn(vv[3] - __half2float(h3));
                *(__half2*)(o0 + 258) = ll;
            }
            if (i0 + 1 < 49) {
                __half* o1 = o0 + 512;
                float2 y0 = unpack2(a10), y1 = unpack2(a11);
                float vv[4] = {y0.x, y0.y, y1.x, y1.y};
                __half h0 = __float2half_rn(vv[0]), h1 = __float2half_rn(vv[1]);
                __half h2 = __float2half_rn(vv[2]), h3 = __float2half_rn(vv[3]);
                __half2 hh, ll;
                hh.x = h0; hh.y = h1; *(__half2*)(o1) = hh;
                hh.x = h2; hh.y = h3; *(__half2*)(o1 + 2) = hh;
                ll.x = __float2half_rn(vv[0] - __half2float(h0));
                ll.y = __float2half_rn(vv[1] - __half2float(h1));
                *(__half2*)(o1 + 256) = ll;
                ll.x = __float2half_rn(vv[2] - __half2float(h2));
                ll.y = __float2half_rn(vv[3] - __half2float(h3));
                *(__half2*)(o1 + 258) = ll;
            }
        }
        __syncthreads();
    }
}

extern "C" void kernel_launch(void* const* d_in, const int* in_sizes, int n_in,
                              void* d_out, int out_size) {
    const float* x      = (const float*)d_in[0];
    const float* mask   = (const float*)d_in[1];
    const float* fg     = (const float*)d_in[2];
    const float* bg     = (const float*)d_in[3];
    const float* qkv_w  = (const float*)d_in[4];
    const float* qkv_b  = (const float*)d_in[5];
    const float* proj_w = (const float*)d_in[6];
    const float* proj_b = (const float*)d_in[7];
    const float* table  = (const float*)d_in[8];
    float* out = (float*)d_out;

    cudaFuncSetAttribute(hgemm<0>, cudaFuncAttributeMaxDynamicSharedMemorySize, GEMM_SMEM);
    cudaFuncSetAttribute(hgemm<1>, cudaFuncAttributeMaxDynamicSharedMemorySize, GEMM_SMEM);

    __half* xh;    cudaGetSymbolAddress((void**)&xh,    g_xh);
    __half* wqkv;  cudaGetSymbolAddress((void**)&wqkv,  g_wqkv);
    __half* wproj; cudaGetSymbolAddress((void**)&wproj, g_wproj);
    __half* ah;    cudaGetSymbolAddress((void**)&ah,    g_ah);

    conv_h<<<(M_ROWS * 64 + 255) / 256, 256>>>(x, xh, M_ROWS);
    conv_h<<<(768 * 64 + 255) / 256, 256>>>(qkv_w, wqkv, 768);
    conv_h<<<(256 * 64 + 255) / 256, 256>>>(proj_w, wproj, 256);
    emb_kernel<<<(64 * NHEAD * NN + 255) / 256, 256>>>(table, mask);

    hgemm<0><<<dim3(6, 784), 256, GEMM_SMEM>>>(xh, wqkv, qkv_b, nullptr);
    attn_kernel<<<B_TOT, 256>>>(fg, bg);
    hgemm<1><<<dim3(2, 784), 256, GEMM_SMEM>>>(ah, wproj, proj_b, out);
}